// round 11
// baseline (speedup 1.0000x reference)
#include <cuda_runtime.h>
#include <stdint.h>
#include <math.h>

#define NIMG 8
#define HH 36
#define WW 36
#define HWTOK 1296
#define HP 38
#define RCH 128
#define NHEAD 8
#define HEADC 16
#define LOG2E 1.44269504088896340736f

typedef unsigned long long ull;

// ---------------- scratch (device globals; zero-init at load) ----------------
__device__ float g_xtp[(size_t)NIMG*RCH*HP*HP];     // padded tanh(in-proj); borders stay 0
__device__ float g_za [(size_t)NIMG*256*HWTOK];     // [z | a]
__device__ float g_q  [(size_t)NIMG*RCH*HWTOK];     // [n][oc][token]
__device__ float g_kT [(size_t)NIMG*NHEAD*HWTOK*HEADC]; // [nh][j][c] transposed
__device__ float g_vT [(size_t)NIMG*NHEAD*HWTOK*HEADC]; // [nh][j][c] transposed
__device__ float g_h  [(size_t)NIMG*RCH*HWTOK];
__device__ float g_pre[3][(size_t)NIMG*RCH*HWTOK];  // gate pre-activations i,g,o

// transposed weights ([in][out], coalesced for GEMM smem fills)
__device__ float g_wt_in [128*128];
__device__ float g_wt_q  [128*128];
__device__ float g_wt_k  [128*128];
__device__ float g_wt_v  [128*128];
__device__ float g_wt_out[128*128];
__device__ float g_wt_i  [256*128];
__device__ float g_wt_g  [256*128];
__device__ float g_wt_o  [256*128];
__device__ float g_wt_conv[1152*128];               // [(ci*9+tap)][o], ci<128 only

// ---------------- helpers ----------------
__device__ __forceinline__ float tanh_fast(float x){
    float r; asm("tanh.approx.f32 %0, %1;" : "=f"(r) : "f"(x)); return r;
}
__device__ __forceinline__ float sigmoid_fast(float x){
    return 0.5f * tanh_fast(0.5f * x) + 0.5f;
}
__device__ __forceinline__ float ex2_fast(float x){
    float r; asm("ex2.approx.f32 %0, %1;" : "=f"(r) : "f"(x)); return r;
}
__device__ __forceinline__ ull pack2(float a, float b){
    ull r; asm("mov.b64 %0, {%1,%2};" : "=l"(r) : "f"(a), "f"(b)); return r;
}
__device__ __forceinline__ ull pack1(float a){
    ull r; asm("mov.b64 %0, {%1,%1};" : "=l"(r) : "f"(a)); return r;
}
__device__ __forceinline__ void unpack2(ull v, float& a, float& b){
    asm("mov.b64 {%0,%1}, %2;" : "=f"(a), "=f"(b) : "l"(v));
}
__device__ __forceinline__ ull mul2(ull a, ull b){
    ull d; asm("mul.rn.f32x2 %0, %1, %2;" : "=l"(d) : "l"(a), "l"(b)); return d;
}
__device__ __forceinline__ ull fma2r(ull a, ull b, ull c){
    ull d; asm("fma.rn.f32x2 %0, %1, %2, %3;" : "=l"(d) : "l"(a), "l"(b), "l"(c)); return d;
}
__device__ __forceinline__ void cpasync16(void* smem_dst, const void* gmem_src, bool pred){
    unsigned int dst = (unsigned int)__cvta_generic_to_shared(smem_dst);
    int sz = pred ? 16 : 0;
    asm volatile("cp.async.cg.shared.global [%0], [%1], 16, %2;"
                 :: "r"(dst), "l"(gmem_src), "r"(sz) : "memory");
}
__device__ __forceinline__ void cp_commit(){
    asm volatile("cp.async.commit_group;" ::: "memory");
}
__device__ __forceinline__ void cp_wait0(){
    asm volatile("cp.async.wait_group 0;" ::: "memory");
}
__device__ __forceinline__ void cp_wait2(){
    asm volatile("cp.async.wait_group 2;" ::: "memory");
}

// ---------------- weight repack ----------------
__global__ void repack_all(const float* __restrict__ w_in, const float* __restrict__ wq,
                           const float* __restrict__ wk,   const float* __restrict__ wv,
                           const float* __restrict__ w_i,  const float* __restrict__ w_g,
                           const float* __restrict__ w_o,  const float* __restrict__ w_out,
                           const float* __restrict__ w_conv)
{
    int idx = blockIdx.x*256 + threadIdx.x;
    if (idx < 5*16384) {
        int m = idx >> 14; int r = idx & 16383; int o = r >> 7; int i = r & 127;
        float v;
        if      (m==0) v = w_in[r];
        else if (m==1) v = wq[r];
        else if (m==2) v = wk[r];
        else if (m==3) v = wv[r];
        else           v = w_out[r];
        float* d = (m==0)?g_wt_in:(m==1)?g_wt_q:(m==2)?g_wt_k:(m==3)?g_wt_v:g_wt_out;
        d[i*128+o] = v;
    } else if (idx < 5*16384 + 3*32768) {
        int r = idx - 5*16384; int m = r >> 15; int rr = r & 32767;
        int o = rr >> 8; int i = rr & 255;    // src [128][256]
        float v = (m==0) ? w_i[rr] : (m==1) ? w_g[rr] : w_o[rr];
        float* d = (m==0)?g_wt_i:(m==1)?g_wt_g:g_wt_o;
        d[i*128+o] = v;
    } else if (idx < 5*16384 + 3*32768 + 147456) {
        int r = idx - (5*16384 + 3*32768);
        int o = r / 1152; int rem = r - o*1152;         // rem = ci*9+tap, ci<128
        g_wt_conv[rem*128 + o] = w_conv[(size_t)o*2304 + rem];
    }
}

// ---------------- async GEMM core: 64 tok x 128 out, 4-stage cp.async, 1 sync/step ----------------
template<int KSTEPS>
__device__ __forceinline__ void gemm_core(const float* __restrict__ xn,
                                          const float* __restrict__ wt,
                                          int t0, ull (&acc2)[4][4],
                                          float (*xs)[16][64], float (*ws)[16][128])
{
    const int tid = threadIdx.x;
    const int tt = tid & 15;
    const int og = tid >> 4;
    const int xi = tid >> 4;                 // x row (k-index within slice)
    const int xq = tid & 15;                 // token quad
    const bool xok = (t0 + xq*4) < HWTOK;
    const int wi = tid >> 5;                 // w row for first half
    const int wq = tid & 31;                 // w quad

    // prologue: stages 0..2
    #pragma unroll
    for (int st=0; st<3; st++){
        int kc = st*16;
        cpasync16(&xs[st][xi][xq*4], xn + (size_t)(kc+xi)*HWTOK + t0 + xq*4, xok);
        cpasync16(&ws[st][wi][wq*4],   wt + (size_t)(kc+wi)*128   + wq*4, true);
        cpasync16(&ws[st][wi+8][wq*4], wt + (size_t)(kc+wi+8)*128 + wq*4, true);
        cp_commit();
    }

    for (int s=0; s<KSTEPS; s++){
        cp_wait2();
        __syncthreads();
        if (s+3 < KSTEPS){
            const int st = (s+3)&3, kc = (s+3)*16;
            cpasync16(&xs[st][xi][xq*4], xn + (size_t)(kc+xi)*HWTOK + t0 + xq*4, xok);
            cpasync16(&ws[st][wi][wq*4],   wt + (size_t)(kc+wi)*128   + wq*4, true);
            cpasync16(&ws[st][wi+8][wq*4], wt + (size_t)(kc+wi+8)*128 + wq*4, true);
        }
        cp_commit();
        const int b = s&3;
        #pragma unroll
        for (int i=0;i<16;i++){
            float4 xv = *(const float4*)&xs[b][i][tt*4];
            ull xb[4] = {pack1(xv.x), pack1(xv.y), pack1(xv.z), pack1(xv.w)};
            ulonglong2 w0 = *(const ulonglong2*)&ws[b][i][og*8];
            ulonglong2 w1 = *(const ulonglong2*)&ws[b][i][og*8+4];
            ull wp[4] = {w0.x, w0.y, w1.x, w1.y};
            #pragma unroll
            for (int p=0;p<4;p++)
                #pragma unroll
                for (int t=0;t<4;t++)
                    acc2[p][t] = fma2r(xb[t], wp[p], acc2[p][t]);
        }
    }
}

// ---------------- in-proj: x -> tanh -> padded g_xtp ----------------
__global__ __launch_bounds__(256) void inproj_kernel(const float* __restrict__ x,
                                                     const float* __restrict__ bias)
{
    __shared__ float xs[4][16][64];
    __shared__ float ws[4][16][128];
    const int n  = blockIdx.y;
    const int t0 = blockIdx.x * 64;
    const int tt = threadIdx.x & 15;
    const int og = threadIdx.x >> 4;
    ull acc2[4][4];
    #pragma unroll
    for (int p=0;p<4;p++) for (int t=0;t<4;t++) acc2[p][t] = 0ull;
    gemm_core<8>(x + (size_t)n*128*HWTOK, g_wt_in, t0, acc2, xs, ws);
    #pragma unroll
    for (int p=0;p<4;p++){
        int oc0 = og*8 + 2*p;
        float b0 = bias[oc0], b1 = bias[oc0+1];
        #pragma unroll
        for (int t=0;t<4;t++){
            int gt = t0 + tt*4 + t;
            if (gt >= HWTOK) continue;
            float v0, v1; unpack2(acc2[p][t], v0, v1);
            int y = gt/WW, xc = gt - y*WW;
            size_t base = (((size_t)n*RCH)*HP + (y+1))*HP + (xc+1);
            g_xtp[base + (size_t)oc0*HP*HP]     = tanh_fast(v0 + b0);
            g_xtp[base + (size_t)(oc0+1)*HP*HP] = tanh_fast(v1 + b1);
        }
    }
}

// ---------------- qkv: z selects matrix; q normal, k/v transposed [nh][j][c] ----------------
__global__ __launch_bounds__(256) void qkv_kernel()
{
    __shared__ float xs[4][16][64];
    __shared__ float ws[4][16][128];
    const int n  = blockIdx.y;
    const int z  = blockIdx.z;
    const int t0 = blockIdx.x * 64;
    const int tt = threadIdx.x & 15;
    const int og = threadIdx.x >> 4;
    const float* wt = (z==0) ? g_wt_q : (z==1) ? g_wt_k : g_wt_v;
    ull acc2[4][4];
    #pragma unroll
    for (int p=0;p<4;p++) for (int t=0;t<4;t++) acc2[p][t] = 0ull;
    gemm_core<8>(g_za + (size_t)n*256*HWTOK, wt, t0, acc2, xs, ws);
    if (z==0){
        #pragma unroll
        for (int p=0;p<4;p++){
            int oc0 = og*8 + 2*p;
            #pragma unroll
            for (int t=0;t<4;t++){
                int gt = t0 + tt*4 + t;
                if (gt >= HWTOK) continue;
                float v0, v1; unpack2(acc2[p][t], v0, v1);
                g_q[((size_t)n*RCH+oc0)*HWTOK+gt]   = v0;
                g_q[((size_t)n*RCH+oc0+1)*HWTOK+gt] = v1;
            }
        }
    } else {
        float* dstT = (z==1) ? g_kT : g_vT;
        #pragma unroll
        for (int p=0;p<4;p++){
            int oc0 = og*8 + 2*p;
            int head = oc0 >> 4, c = oc0 & 15;
            #pragma unroll
            for (int t=0;t<4;t++){
                int gt = t0 + tt*4 + t;
                if (gt >= HWTOK) continue;
                float v0, v1; unpack2(acc2[p][t], v0, v1);
                float2 val; val.x = v0; val.y = v1;
                *(float2*)&dstT[(((size_t)(n*NHEAD + head))*HWTOK + gt)*HEADC + c] = val;
            }
        }
    }
}

// ---------------- gates GEMM: z in {i,g,o}; raw store to g_pre ----------------
__global__ __launch_bounds__(256) void gates_gemm_kernel()
{
    __shared__ float xs[4][16][64];
    __shared__ float ws[4][16][128];
    const int n  = blockIdx.y;
    const int z  = blockIdx.z;
    const int t0 = blockIdx.x * 64;
    const int tt = threadIdx.x & 15;
    const int og = threadIdx.x >> 4;
    const float* wt = (z==0) ? g_wt_i : (z==1) ? g_wt_g : g_wt_o;
    float* dst = g_pre[z];
    ull acc2[4][4];
    #pragma unroll
    for (int p=0;p<4;p++) for (int t=0;t<4;t++) acc2[p][t] = 0ull;
    gemm_core<16>(g_za + (size_t)n*256*HWTOK, wt, t0, acc2, xs, ws);
    #pragma unroll
    for (int p=0;p<4;p++){
        int oc0 = og*8 + 2*p;
        #pragma unroll
        for (int t=0;t<4;t++){
            int gt = t0 + tt*4 + t;
            if (gt >= HWTOK) continue;
            float v0, v1; unpack2(acc2[p][t], v0, v1);
            dst[((size_t)n*RCH+oc0)*HWTOK+gt]   = v0;
            dst[((size_t)n*RCH+oc0+1)*HWTOK+gt] = v1;
        }
    }
}

// ---------------- LSTM activation: h = sigm(o) * tanh(sigm(i)*tanh(g)) ----------------
#define ACT_N4 (NIMG*RCH*(HWTOK/4))
__global__ __launch_bounds__(256) void lstm_act_kernel(const float* __restrict__ bi,
                                                       const float* __restrict__ bg,
                                                       const float* __restrict__ bo)
{
    int i4 = blockIdx.x*256 + threadIdx.x;
    if (i4 >= ACT_N4) return;
    int oc = (i4 / (HWTOK/4)) & 127;
    float bbi = bi[oc], bbg = bg[oc], bbo = bo[oc];
    float4 pi = ((const float4*)g_pre[0])[i4];
    float4 pg = ((const float4*)g_pre[1])[i4];
    float4 po = ((const float4*)g_pre[2])[i4];
    float4 r;
    r.x = sigmoid_fast(po.x+bbo) * tanh_fast(sigmoid_fast(pi.x+bbi) * tanh_fast(pg.x+bbg));
    r.y = sigmoid_fast(po.y+bbo) * tanh_fast(sigmoid_fast(pi.y+bbi) * tanh_fast(pg.y+bbg));
    r.z = sigmoid_fast(po.z+bbo) * tanh_fast(sigmoid_fast(pi.z+bbi) * tanh_fast(pg.z+bbg));
    r.w = sigmoid_fast(po.w+bbo) * tanh_fast(sigmoid_fast(pi.w+bbi) * tanh_fast(pg.w+bbg));
    ((float4*)g_h)[i4] = r;
}

// ---------------- out-proj ----------------
__global__ __launch_bounds__(256) void outproj_kernel(const float* __restrict__ bias,
                                                      float* __restrict__ outx)
{
    __shared__ float xs[4][16][64];
    __shared__ float ws[4][16][128];
    const int n  = blockIdx.y;
    const int t0 = blockIdx.x * 64;
    const int tt = threadIdx.x & 15;
    const int og = threadIdx.x >> 4;
    ull acc2[4][4];
    #pragma unroll
    for (int p=0;p<4;p++) for (int t=0;t<4;t++) acc2[p][t] = 0ull;
    gemm_core<8>(g_h + (size_t)n*128*HWTOK, g_wt_out, t0, acc2, xs, ws);
    #pragma unroll
    for (int p=0;p<4;p++){
        int oc0 = og*8 + 2*p;
        float b0 = bias[oc0], b1 = bias[oc0+1];
        #pragma unroll
        for (int t=0;t<4;t++){
            int gt = t0 + tt*4 + t;
            if (gt >= HWTOK) continue;
            float v0, v1; unpack2(acc2[p][t], v0, v1);
            outx[((size_t)n*RCH+oc0)*HWTOK+gt]   = v0 + b0;
            outx[((size_t)n*RCH+oc0+1)*HWTOK+gt] = v1 + b1;
        }
    }
}

// ---------------- conv3x3 (2 output rows/block, double-buffered) ----------------
__global__ void conv3x3_kernel(const float* __restrict__ bias)
{
    __shared__ float xs[2][8][4][40];
    __shared__ float ws[2][8][9][128];
    const int n  = blockIdx.y;
    const int y0 = blockIdx.x*2;
    const int tid = threadIdx.x;        // 288 threads
    const int tg = tid % 9;
    const int og = tid / 9;
    ull acc2[2][2][4];
    #pragma unroll
    for (int yr=0;yr<2;yr++) for (int p=0;p<2;p++) for (int t=0;t<4;t++) acc2[yr][p][t]=0ull;

    const float* xp = g_xtp + (size_t)n*RCH*HP*HP;
    float xr[5]; float4 wr[8];

    #pragma unroll
    for (int r=0;r<5;r++){
        int idx = tid + r*288;
        if (idx < 1216){
            int ci = idx/152, rem = idx - ci*152, dy = rem/38, cx = rem - dy*38;
            xr[r] = xp[(size_t)ci*HP*HP + (y0+dy)*HP + cx];
        }
    }
    #pragma unroll
    for (int r=0;r<8;r++) wr[r] = ((const float4*)g_wt_conv)[tid + r*288];
    #pragma unroll
    for (int r=0;r<5;r++){
        int idx = tid + r*288;
        if (idx < 1216){
            int ci = idx/152, rem = idx - ci*152, dy = rem/38, cx = rem - dy*38;
            xs[0][ci][dy][cx] = xr[r];
        }
    }
    #pragma unroll
    for (int r=0;r<8;r++) ((float4*)ws[0])[tid + r*288] = wr[r];
    __syncthreads();

    for (int s=0; s<16; s++){
        const int b = s&1;
        if (s<15){
            const int kc=(s+1)*8;
            #pragma unroll
            for (int r=0;r<5;r++){
                int idx = tid + r*288;
                if (idx < 1216){
                    int ci = idx/152, rem = idx - ci*152, dy = rem/38, cx = rem - dy*38;
                    xr[r] = xp[(size_t)(kc+ci)*HP*HP + (y0+dy)*HP + cx];
                }
            }
            #pragma unroll
            for (int r=0;r<8;r++) wr[r] = ((const float4*)(g_wt_conv + kc*1152))[tid + r*288];
        }
        #pragma unroll
        for (int i=0;i<8;i++){
            ull xb[4][6];
            #pragma unroll
            for (int dy=0; dy<4; dy++){
                float4 x4 = *(const float4*)&xs[b][i][dy][tg*4];
                float2 x2 = *(const float2*)&xs[b][i][dy][tg*4+4];
                xb[dy][0]=pack1(x4.x); xb[dy][1]=pack1(x4.y); xb[dy][2]=pack1(x4.z);
                xb[dy][3]=pack1(x4.w); xb[dy][4]=pack1(x2.x); xb[dy][5]=pack1(x2.y);
            }
            #pragma unroll
            for (int dy=0;dy<3;dy++)
                #pragma unroll
                for (int dx=0;dx<3;dx++){
                    ulonglong2 w2 = *(const ulonglong2*)&ws[b][i][dy*3+dx][og*4];
                    #pragma unroll
                    for (int yr=0;yr<2;yr++)
                        #pragma unroll
                        for (int t=0;t<4;t++){
                            acc2[yr][0][t] = fma2r(xb[dy+yr][t+dx], w2.x, acc2[yr][0][t]);
                            acc2[yr][1][t] = fma2r(xb[dy+yr][t+dx], w2.y, acc2[yr][1][t]);
                        }
                }
        }
        if (s<15){
            const int nb = b^1;
            #pragma unroll
            for (int r=0;r<5;r++){
                int idx = tid + r*288;
                if (idx < 1216){
                    int ci = idx/152, rem = idx - ci*152, dy = rem/38, cx = rem - dy*38;
                    xs[nb][ci][dy][cx] = xr[r];
                }
            }
            #pragma unroll
            for (int r=0;r<8;r++) ((float4*)ws[nb])[tid + r*288] = wr[r];
        }
        __syncthreads();
    }

    #pragma unroll
    for (int yr=0;yr<2;yr++){
        int y = y0 + yr;
        #pragma unroll
        for (int p=0;p<2;p++){
            int oc0 = og*4 + 2*p;
            float b0 = bias[oc0], b1 = bias[oc0+1];
            #pragma unroll
            for (int t=0;t<4;t++){
                int xc = tg*4+t;
                float v0, v1; unpack2(acc2[yr][p][t], v0, v1);
                g_za[((size_t)n*256 + oc0)*HWTOK + y*WW + xc]   = v0 + b0;
                g_za[((size_t)n*256 + oc0+1)*HWTOK + y*WW + xc] = v1 + b1;
            }
        }
    }
}

// ---------------- attention: j-tiled cp.async K/V stream, 2q/thread ----------------
#define ATTN_THREADS 224
#define ATTN_ACT 216
#define JT 162
#define NJT (HWTOK/JT)          // 8 tiles

__global__ __launch_bounds__(ATTN_THREADS) void attn_kernel()
{
    __shared__ float Ks[2][JT*HEADC];   // [stage][j][c]
    __shared__ float Vs[2][JT*HEADC];
    const int nh = blockIdx.y; const int n = nh >> 3; const int h = nh & 7;
    const int tid = threadIdx.x;
    const float* kp = g_kT + (size_t)nh*HWTOK*HEADC;
    const float* vp = g_vT + (size_t)nh*HWTOK*HEADC;

    // load tile 0
    #pragma unroll
    for (int r=0;r<3;r++){
        int idx = tid + r*ATTN_THREADS;
        if (idx < (JT*HEADC)/4){
            cpasync16(&Ks[0][idx*4], kp + idx*4, true);
            cpasync16(&Vs[0][idx*4], vp + idx*4, true);
        }
    }
    cp_commit();

    // q state
    const int q0 = blockIdx.x*432 + (tid < ATTN_ACT ? tid : ATTN_ACT-1);
    const int q1 = q0 + ATTN_ACT;
    const float* qp = g_q + ((size_t)n*RCH + h*HEADC)*HWTOK;
    ull q2[2][8], a2[2][8]; float l[2];
    #pragma unroll
    for (int u=0;u<2;u++){
        int q = (u==0) ? q0 : q1;
        #pragma unroll
        for (int p=0;p<8;p++){
            q2[u][p] = pack2(qp[(size_t)(2*p)*HWTOK+q]*LOG2E,
                             qp[(size_t)(2*p+1)*HWTOK+q]*LOG2E);
            a2[u][p] = 0ull;
        }
        l[u] = 0.f;
    }

    for (int jt=0; jt<NJT; jt++){
        cp_wait0();
        __syncthreads();
        if (jt+1 < NJT){
            const int st = (jt+1)&1;
            const size_t base = (size_t)(jt+1)*JT*HEADC;
            #pragma unroll
            for (int r=0;r<3;r++){
                int idx = tid + r*ATTN_THREADS;
                if (idx < (JT*HEADC)/4){
                    cpasync16(&Ks[st][idx*4], kp + base + idx*4, true);
                    cpasync16(&Vs[st][idx*4], vp + base + idx*4, true);
                }
            }
        }
        cp_commit();
        const int b = jt&1;
        #pragma unroll 2
        for (int j=0;j<JT;j++){
            const ulonglong2* kr = (const ulonglong2*)(&Ks[b][j*HEADC]);
            ulonglong2 k0 = kr[0], k1 = kr[1], k2 = kr[2], k3 = kr[3];
            float e[2];
            #pragma unroll
            for (int u=0;u<2;u++){
                ull s = mul2(q2[u][0], k0.x);
                s = fma2r(q2[u][1], k0.y, s);
                s = fma2r(q2[u][2], k1.x, s);
                s = fma2r(q2[u][3], k1.y, s);
                s = fma2r(q2[u][4], k2.x, s);
                s = fma2r(q2[u][5], k2.y, s);
                s = fma2r(q2[u][6], k3.x, s);
                s = fma2r(q2[u][7], k3.y, s);
                float s0, s1; unpack2(s, s0, s1);
                e[u] = ex2_fast(s0 + s1);
                l[u] += e[u];
            }
            const ulonglong2* vr = (const ulonglong2*)(&Vs[b][j*HEADC]);
            ulonglong2 v0 = vr[0], v1 = vr[1], v2 = vr[2], v3 = vr[3];
            ull vv[8] = {v0.x,v0.y,v1.x,v1.y,v2.x,v2.y,v3.x,v3.y};
            #pragma unroll
            for (int u=0;u<2;u++){
                ull eb = pack1(e[u]);
                #pragma unroll
                for (int p=0;p<8;p++) a2[u][p] = fma2r(eb, vv[p], a2[u][p]);
            }
        }
        __syncthreads();
    }

    if (tid >= ATTN_ACT) return;
    float* ap = g_za + ((size_t)n*256 + 128 + h*HEADC)*HWTOK;
    #pragma unroll
    for (int u=0;u<2;u++){
        int q = (u==0) ? q0 : q1;
        float inv = 1.f / l[u];
        #pragma unroll
        for (int p=0;p<8;p++){
            float lo, hi; unpack2(a2[u][p], lo, hi);
            ap[(size_t)(2*p)*HWTOK + q]   = lo*inv;
            ap[(size_t)(2*p+1)*HWTOK + q] = hi*inv;
        }
    }
}

// ---------------- launch ----------------
extern "C" void kernel_launch(void* const* d_in, const int* in_sizes, int n_in,
                              void* d_out, int out_size)
{
    const float* x      = (const float*)d_in[0];
    const float* w_in   = (const float*)d_in[1];
    const float* b_in   = (const float*)d_in[2];
    const float* w_conv = (const float*)d_in[3];
    const float* b_conv = (const float*)d_in[4];
    const float* wq     = (const float*)d_in[5];
    const float* wk     = (const float*)d_in[6];
    const float* wv     = (const float*)d_in[7];
    const float* w_i    = (const float*)d_in[8];
    const float* b_i    = (const float*)d_in[9];
    // d_in[10], d_in[11]: w_f/b_f unused (first timestep: f*c0 == 0)
    const float* w_g    = (const float*)d_in[12];
    const float* b_g    = (const float*)d_in[13];
    const float* w_o    = (const float*)d_in[14];
    const float* b_o    = (const float*)d_in[15];
    const float* w_out  = (const float*)d_in[16];
    const float* b_out  = (const float*)d_in[17];
    float* out = (float*)d_out;

    repack_all<<<1280,256>>>(w_in, wq, wk, wv, w_i, w_g, w_o, w_out, w_conv);

    inproj_kernel<<<dim3(21,NIMG),256>>>(x, b_in);                   // -> g_xtp
    conv3x3_kernel<<<dim3(18,NIMG),288>>>(b_conv);                   // -> g_za[:, :128]
    qkv_kernel<<<dim3(21,NIMG,3),256>>>();                           // -> g_q/g_kT/g_vT
    attn_kernel<<<dim3(3, NIMG*NHEAD), ATTN_THREADS>>>();            // -> g_za[:,128:]
    gates_gemm_kernel<<<dim3(21,NIMG,3),256>>>();                    // -> g_pre
    lstm_act_kernel<<<(ACT_N4+255)/256,256>>>(b_i, b_g, b_o);        // -> g_h
    outproj_kernel<<<dim3(21,NIMG),256>>>(b_out, out);               // -> d_out
}

// round 12
// speedup vs baseline: 1.0976x; 1.0976x over previous
#include <cuda_runtime.h>
#include <stdint.h>
#include <math.h>

#define NIMG 8
#define HH 36
#define WW 36
#define HWTOK 1296
#define HP 38
#define RCH 128
#define NHEAD 8
#define HEADC 16
#define LOG2E 1.44269504088896340736f

typedef unsigned long long ull;

// ---------------- scratch (device globals; zero-init at load) ----------------
__device__ float g_xtp[(size_t)NIMG*RCH*HP*HP];     // padded tanh(in-proj); borders stay 0
__device__ float g_za [(size_t)NIMG*256*HWTOK];     // [z | a]
__device__ float g_q  [(size_t)NIMG*RCH*HWTOK];
__device__ float g_k  [(size_t)NIMG*RCH*HWTOK];
__device__ float g_v  [(size_t)NIMG*RCH*HWTOK];
__device__ float g_h  [(size_t)NIMG*RCH*HWTOK];
__device__ float g_pre[3][(size_t)NIMG*RCH*HWTOK];  // gate pre-activations i,g,o

// transposed weights ([in][out], coalesced for GEMM smem fills)
__device__ float g_wt_in [128*128];
__device__ float g_wt_q  [128*128];
__device__ float g_wt_k  [128*128];
__device__ float g_wt_v  [128*128];
__device__ float g_wt_out[128*128];
__device__ float g_wt_i  [256*128];
__device__ float g_wt_g  [256*128];
__device__ float g_wt_o  [256*128];
__device__ float g_wt_conv[1152*128];               // [(ci*9+tap)][o], ci<128 only

// ---------------- helpers ----------------
__device__ __forceinline__ float tanh_fast(float x){
    float r; asm("tanh.approx.f32 %0, %1;" : "=f"(r) : "f"(x)); return r;
}
__device__ __forceinline__ float sigmoid_fast(float x){
    return 0.5f * tanh_fast(0.5f * x) + 0.5f;
}
__device__ __forceinline__ float ex2_fast(float x){
    float r; asm("ex2.approx.f32 %0, %1;" : "=f"(r) : "f"(x)); return r;
}
__device__ __forceinline__ ull pack2(float a, float b){
    ull r; asm("mov.b64 %0, {%1,%2};" : "=l"(r) : "f"(a), "f"(b)); return r;
}
__device__ __forceinline__ ull pack1(float a){
    ull r; asm("mov.b64 %0, {%1,%1};" : "=l"(r) : "f"(a)); return r;
}
__device__ __forceinline__ void unpack2(ull v, float& a, float& b){
    asm("mov.b64 {%0,%1}, %2;" : "=f"(a), "=f"(b) : "l"(v));
}
__device__ __forceinline__ ull mul2(ull a, ull b){
    ull d; asm("mul.rn.f32x2 %0, %1, %2;" : "=l"(d) : "l"(a), "l"(b)); return d;
}
__device__ __forceinline__ ull fma2r(ull a, ull b, ull c){
    ull d; asm("fma.rn.f32x2 %0, %1, %2, %3;" : "=l"(d) : "l"(a), "l"(b), "l"(c)); return d;
}
__device__ __forceinline__ void cpasync16(void* smem_dst, const void* gmem_src, bool pred){
    unsigned int dst = (unsigned int)__cvta_generic_to_shared(smem_dst);
    int sz = pred ? 16 : 0;
    asm volatile("cp.async.cg.shared.global [%0], [%1], 16, %2;"
                 :: "r"(dst), "l"(gmem_src), "r"(sz) : "memory");
}
__device__ __forceinline__ void cp_commit(){
    asm volatile("cp.async.commit_group;" ::: "memory");
}
__device__ __forceinline__ void cp_wait0(){
    asm volatile("cp.async.wait_group 0;" ::: "memory");
}
__device__ __forceinline__ void cp_wait1(){
    asm volatile("cp.async.wait_group 1;" ::: "memory");
}

// ---------------- weight repack ----------------
__global__ void repack_all(const float* __restrict__ w_in, const float* __restrict__ wq,
                           const float* __restrict__ wk,   const float* __restrict__ wv,
                           const float* __restrict__ w_i,  const float* __restrict__ w_g,
                           const float* __restrict__ w_o,  const float* __restrict__ w_out,
                           const float* __restrict__ w_conv)
{
    int idx = blockIdx.x*256 + threadIdx.x;
    if (idx < 5*16384) {
        int m = idx >> 14; int r = idx & 16383; int o = r >> 7; int i = r & 127;
        float v;
        if      (m==0) v = w_in[r];
        else if (m==1) v = wq[r];
        else if (m==2) v = wk[r];
        else if (m==3) v = wv[r];
        else           v = w_out[r];
        float* d = (m==0)?g_wt_in:(m==1)?g_wt_q:(m==2)?g_wt_k:(m==3)?g_wt_v:g_wt_out;
        d[i*128+o] = v;
    } else if (idx < 5*16384 + 3*32768) {
        int r = idx - 5*16384; int m = r >> 15; int rr = r & 32767;
        int o = rr >> 8; int i = rr & 255;    // src [128][256]
        float v = (m==0) ? w_i[rr] : (m==1) ? w_g[rr] : w_o[rr];
        float* d = (m==0)?g_wt_i:(m==1)?g_wt_g:g_wt_o;
        d[i*128+o] = v;
    } else if (idx < 5*16384 + 3*32768 + 147456) {
        int r = idx - (5*16384 + 3*32768);
        int o = r / 1152; int rem = r - o*1152;         // rem = ci*9+tap, ci<128
        g_wt_conv[rem*128 + o] = w_conv[(size_t)o*2304 + rem];
    }
}

// ---------------- async GEMM core: 64 tok x 128 out, 3-stage cp.async (R9) ----------------
template<int KSTEPS>
__device__ __forceinline__ void gemm_core(const float* __restrict__ xn,
                                          const float* __restrict__ wt,
                                          int t0, ull (&acc2)[4][4],
                                          float (*xs)[16][64], float (*ws)[16][128])
{
    const int tid = threadIdx.x;
    const int tt = tid & 15;
    const int og = tid >> 4;
    const int xi = tid >> 4;                 // x row (k-index within slice)
    const int xq = tid & 15;                 // token quad
    const bool xok = (t0 + xq*4) < HWTOK;
    const int wi = tid >> 5;                 // w row for first half
    const int wq = tid & 31;                 // w quad

    // prologue: stages 0 and 1
    for (int st=0; st<2; st++){
        int kc = st*16;
        cpasync16(&xs[st][xi][xq*4], xn + (size_t)(kc+xi)*HWTOK + t0 + xq*4, xok);
        cpasync16(&ws[st][wi][wq*4],   wt + (size_t)(kc+wi)*128   + wq*4, true);
        cpasync16(&ws[st][wi+8][wq*4], wt + (size_t)(kc+wi+8)*128 + wq*4, true);
        cp_commit();
    }

    for (int s=0; s<KSTEPS; s++){
        cp_wait1();
        __syncthreads();
        if (s+2 < KSTEPS){
            const int st = (s+2)%3, kc = (s+2)*16;
            cpasync16(&xs[st][xi][xq*4], xn + (size_t)(kc+xi)*HWTOK + t0 + xq*4, xok);
            cpasync16(&ws[st][wi][wq*4],   wt + (size_t)(kc+wi)*128   + wq*4, true);
            cpasync16(&ws[st][wi+8][wq*4], wt + (size_t)(kc+wi+8)*128 + wq*4, true);
        }
        cp_commit();
        const int b = s%3;
        #pragma unroll
        for (int i=0;i<16;i++){
            float4 xv = *(const float4*)&xs[b][i][tt*4];
            ull xb[4] = {pack1(xv.x), pack1(xv.y), pack1(xv.z), pack1(xv.w)};
            ulonglong2 w0 = *(const ulonglong2*)&ws[b][i][og*8];
            ulonglong2 w1 = *(const ulonglong2*)&ws[b][i][og*8+4];
            ull wp[4] = {w0.x, w0.y, w1.x, w1.y};
            #pragma unroll
            for (int p=0;p<4;p++)
                #pragma unroll
                for (int t=0;t<4;t++)
                    acc2[p][t] = fma2r(xb[t], wp[p], acc2[p][t]);
        }
        __syncthreads();
    }
}

// ---------------- in-proj: x -> tanh -> padded g_xtp ----------------
__global__ __launch_bounds__(256) void inproj_kernel(const float* __restrict__ x,
                                                     const float* __restrict__ bias)
{
    __shared__ float xs[3][16][64];
    __shared__ float ws[3][16][128];
    const int n  = blockIdx.y;
    const int t0 = blockIdx.x * 64;
    const int tt = threadIdx.x & 15;
    const int og = threadIdx.x >> 4;
    ull acc2[4][4];
    #pragma unroll
    for (int p=0;p<4;p++) for (int t=0;t<4;t++) acc2[p][t] = 0ull;
    gemm_core<8>(x + (size_t)n*128*HWTOK, g_wt_in, t0, acc2, xs, ws);
    #pragma unroll
    for (int p=0;p<4;p++){
        int oc0 = og*8 + 2*p;
        float b0 = bias[oc0], b1 = bias[oc0+1];
        #pragma unroll
        for (int t=0;t<4;t++){
            int gt = t0 + tt*4 + t;
            if (gt >= HWTOK) continue;
            float v0, v1; unpack2(acc2[p][t], v0, v1);
            int y = gt/WW, xc = gt - y*WW;
            size_t base = (((size_t)n*RCH)*HP + (y+1))*HP + (xc+1);
            g_xtp[base + (size_t)oc0*HP*HP]     = tanh_fast(v0 + b0);
            g_xtp[base + (size_t)(oc0+1)*HP*HP] = tanh_fast(v1 + b1);
        }
    }
}

// ---------------- qkv: z selects matrix; raw store ----------------
__global__ __launch_bounds__(256) void qkv_kernel()
{
    __shared__ float xs[3][16][64];
    __shared__ float ws[3][16][128];
    const int n  = blockIdx.y;
    const int z  = blockIdx.z;
    const int t0 = blockIdx.x * 64;
    const int tt = threadIdx.x & 15;
    const int og = threadIdx.x >> 4;
    const float* wt = (z==0) ? g_wt_q : (z==1) ? g_wt_k : g_wt_v;
    float* dst      = (z==0) ? g_q    : (z==1) ? g_k    : g_v;
    ull acc2[4][4];
    #pragma unroll
    for (int p=0;p<4;p++) for (int t=0;t<4;t++) acc2[p][t] = 0ull;
    gemm_core<8>(g_za + (size_t)n*256*HWTOK, wt, t0, acc2, xs, ws);
    #pragma unroll
    for (int p=0;p<4;p++){
        int oc0 = og*8 + 2*p;
        #pragma unroll
        for (int t=0;t<4;t++){
            int gt = t0 + tt*4 + t;
            if (gt >= HWTOK) continue;
            float v0, v1; unpack2(acc2[p][t], v0, v1);
            dst[((size_t)n*RCH+oc0)*HWTOK+gt]   = v0;
            dst[((size_t)n*RCH+oc0+1)*HWTOK+gt] = v1;
        }
    }
}

// ---------------- gates GEMM: z in {i,g,o}; raw store to g_pre ----------------
__global__ __launch_bounds__(256) void gates_gemm_kernel()
{
    __shared__ float xs[3][16][64];
    __shared__ float ws[3][16][128];
    const int n  = blockIdx.y;
    const int z  = blockIdx.z;
    const int t0 = blockIdx.x * 64;
    const int tt = threadIdx.x & 15;
    const int og = threadIdx.x >> 4;
    const float* wt = (z==0) ? g_wt_i : (z==1) ? g_wt_g : g_wt_o;
    float* dst = g_pre[z];
    ull acc2[4][4];
    #pragma unroll
    for (int p=0;p<4;p++) for (int t=0;t<4;t++) acc2[p][t] = 0ull;
    gemm_core<16>(g_za + (size_t)n*256*HWTOK, wt, t0, acc2, xs, ws);
    #pragma unroll
    for (int p=0;p<4;p++){
        int oc0 = og*8 + 2*p;
        #pragma unroll
        for (int t=0;t<4;t++){
            int gt = t0 + tt*4 + t;
            if (gt >= HWTOK) continue;
            float v0, v1; unpack2(acc2[p][t], v0, v1);
            dst[((size_t)n*RCH+oc0)*HWTOK+gt]   = v0;
            dst[((size_t)n*RCH+oc0+1)*HWTOK+gt] = v1;
        }
    }
}

// ---------------- LSTM activation: h = sigm(o) * tanh(sigm(i)*tanh(g)) ----------------
#define ACT_N4 (NIMG*RCH*(HWTOK/4))
__global__ __launch_bounds__(256) void lstm_act_kernel(const float* __restrict__ bi,
                                                       const float* __restrict__ bg,
                                                       const float* __restrict__ bo)
{
    int i4 = blockIdx.x*256 + threadIdx.x;
    if (i4 >= ACT_N4) return;
    int oc = (i4 / (HWTOK/4)) & 127;
    float bbi = bi[oc], bbg = bg[oc], bbo = bo[oc];
    float4 pi = ((const float4*)g_pre[0])[i4];
    float4 pg = ((const float4*)g_pre[1])[i4];
    float4 po = ((const float4*)g_pre[2])[i4];
    float4 r;
    r.x = sigmoid_fast(po.x+bbo) * tanh_fast(sigmoid_fast(pi.x+bbi) * tanh_fast(pg.x+bbg));
    r.y = sigmoid_fast(po.y+bbo) * tanh_fast(sigmoid_fast(pi.y+bbi) * tanh_fast(pg.y+bbg));
    r.z = sigmoid_fast(po.z+bbo) * tanh_fast(sigmoid_fast(pi.z+bbi) * tanh_fast(pg.z+bbg));
    r.w = sigmoid_fast(po.w+bbo) * tanh_fast(sigmoid_fast(pi.w+bbi) * tanh_fast(pg.w+bbg));
    ((float4*)g_h)[i4] = r;
}

// ---------------- out-proj ----------------
__global__ __launch_bounds__(256) void outproj_kernel(const float* __restrict__ bias,
                                                      float* __restrict__ outx)
{
    __shared__ float xs[3][16][64];
    __shared__ float ws[3][16][128];
    const int n  = blockIdx.y;
    const int t0 = blockIdx.x * 64;
    const int tt = threadIdx.x & 15;
    const int og = threadIdx.x >> 4;
    ull acc2[4][4];
    #pragma unroll
    for (int p=0;p<4;p++) for (int t=0;t<4;t++) acc2[p][t] = 0ull;
    gemm_core<8>(g_h + (size_t)n*128*HWTOK, g_wt_out, t0, acc2, xs, ws);
    #pragma unroll
    for (int p=0;p<4;p++){
        int oc0 = og*8 + 2*p;
        float b0 = bias[oc0], b1 = bias[oc0+1];
        #pragma unroll
        for (int t=0;t<4;t++){
            int gt = t0 + tt*4 + t;
            if (gt >= HWTOK) continue;
            float v0, v1; unpack2(acc2[p][t], v0, v1);
            outx[((size_t)n*RCH+oc0)*HWTOK+gt]   = v0 + b0;
            outx[((size_t)n*RCH+oc0+1)*HWTOK+gt] = v1 + b1;
        }
    }
}

// ---------------- conv3x3: weights via cp.async, x via regs ----------------
__global__ void conv3x3_kernel(const float* __restrict__ bias)
{
    __shared__ float xs[2][8][4][40];
    __shared__ float ws[2][8][9][128];
    const int n  = blockIdx.y;
    const int y0 = blockIdx.x*2;
    const int tid = threadIdx.x;        // 288 threads
    const int tg = tid % 9;
    const int og = tid / 9;
    ull acc2[2][2][4];
    #pragma unroll
    for (int yr=0;yr<2;yr++) for (int p=0;p<2;p++) for (int t=0;t<4;t++) acc2[yr][p][t]=0ull;

    const float* xp = g_xtp + (size_t)n*RCH*HP*HP;
    float xr[5];

    // prologue: stage 0
    #pragma unroll
    for (int r=0;r<5;r++){
        int idx = tid + r*288;
        if (idx < 1216){
            int ci = idx/152, rem = idx - ci*152, dy = rem/38, cx = rem - dy*38;
            xs[0][ci][dy][cx] = xp[(size_t)ci*HP*HP + (y0+dy)*HP + cx];
        }
    }
    #pragma unroll
    for (int r=0;r<8;r++)
        cpasync16(&((float4*)ws[0])[tid + r*288], ((const float4*)g_wt_conv) + tid + r*288, true);
    cp_commit();
    cp_wait0();
    __syncthreads();

    for (int s=0; s<16; s++){
        const int b = s&1, nb = b^1;
        if (s<15){
            const int kc=(s+1)*8;
            #pragma unroll
            for (int r=0;r<5;r++){
                int idx = tid + r*288;
                if (idx < 1216){
                    int ci = idx/152, rem = idx - ci*152, dy = rem/38, cx = rem - dy*38;
                    xr[r] = xp[(size_t)(kc+ci)*HP*HP + (y0+dy)*HP + cx];
                }
            }
            #pragma unroll
            for (int r=0;r<8;r++)
                cpasync16(&((float4*)ws[nb])[tid + r*288],
                          ((const float4*)(g_wt_conv + kc*1152)) + tid + r*288, true);
            cp_commit();
        }
        #pragma unroll
        for (int i=0;i<8;i++){
            ull xb[4][6];
            #pragma unroll
            for (int dy=0; dy<4; dy++){
                float4 x4 = *(const float4*)&xs[b][i][dy][tg*4];
                float2 x2 = *(const float2*)&xs[b][i][dy][tg*4+4];
                xb[dy][0]=pack1(x4.x); xb[dy][1]=pack1(x4.y); xb[dy][2]=pack1(x4.z);
                xb[dy][3]=pack1(x4.w); xb[dy][4]=pack1(x2.x); xb[dy][5]=pack1(x2.y);
            }
            #pragma unroll
            for (int dy=0;dy<3;dy++)
                #pragma unroll
                for (int dx=0;dx<3;dx++){
                    ulonglong2 w2 = *(const ulonglong2*)&ws[b][i][dy*3+dx][og*4];
                    #pragma unroll
                    for (int yr=0;yr<2;yr++)
                        #pragma unroll
                        for (int t=0;t<4;t++){
                            acc2[yr][0][t] = fma2r(xb[dy+yr][t+dx], w2.x, acc2[yr][0][t]);
                            acc2[yr][1][t] = fma2r(xb[dy+yr][t+dx], w2.y, acc2[yr][1][t]);
                        }
                }
        }
        if (s<15){
            #pragma unroll
            for (int r=0;r<5;r++){
                int idx = tid + r*288;
                if (idx < 1216){
                    int ci = idx/152, rem = idx - ci*152, dy = rem/38, cx = rem - dy*38;
                    xs[nb][ci][dy][cx] = xr[r];
                }
            }
            cp_wait0();
        }
        __syncthreads();
    }

    #pragma unroll
    for (int yr=0;yr<2;yr++){
        int y = y0 + yr;
        #pragma unroll
        for (int p=0;p<2;p++){
            int oc0 = og*4 + 2*p;
            float b0 = bias[oc0], b1 = bias[oc0+1];
            #pragma unroll
            for (int t=0;t<4;t++){
                int xc = tg*4+t;
                float v0, v1; unpack2(acc2[yr][p][t], v0, v1);
                g_za[((size_t)n*256 + oc0)*HWTOK + y*WW + xc]   = v0 + b0;
                g_za[((size_t)n*256 + oc0+1)*HWTOK + y*WW + xc] = v1 + b1;
            }
        }
    }
}

// ---------------- attention: K,V smem-resident, 11 warps, 2 q/thread (R4/R9 config) ----------------
#define ATTN_THREADS 352
#define ATTN_ACT 324
#define ATTN_SMEM (2*HWTOK*HEADC*4)

__global__ void attn_kernel()
{
    extern __shared__ float sm[];
    float* Ks = sm;                       // [1296][16]
    float* Vs = sm + HWTOK*HEADC;
    const int nh = blockIdx.y; const int n = nh >> 3; const int h = nh & 7;
    const int tid = threadIdx.x;
    const float* kp = g_k + ((size_t)n*RCH + h*HEADC)*HWTOK;
    const float* vp = g_v + ((size_t)n*RCH + h*HEADC)*HWTOK;
    #pragma unroll
    for (int c=0;c<HEADC;c++){
        for (int j=tid;j<HWTOK;j+=ATTN_THREADS){
            Ks[j*HEADC+c] = kp[(size_t)c*HWTOK+j];
            Vs[j*HEADC+c] = vp[(size_t)c*HWTOK+j];
        }
    }
    __syncthreads();
    if (tid >= ATTN_ACT) return;

    const int q0 = blockIdx.x*648 + tid;     // q0, q0+324
    const float* qp = g_q + ((size_t)n*RCH + h*HEADC)*HWTOK;
    ull q2[2][8], a2[2][8]; float l[2];
    #pragma unroll
    for (int u=0;u<2;u++){
        int q = q0 + u*ATTN_ACT;
        #pragma unroll
        for (int p=0;p<8;p++){
            q2[u][p] = pack2(qp[(size_t)(2*p)*HWTOK+q]*LOG2E,
                             qp[(size_t)(2*p+1)*HWTOK+q]*LOG2E);
            a2[u][p] = 0ull;
        }
        l[u] = 0.f;
    }
    #pragma unroll 2
    for (int j=0;j<HWTOK;j++){
        const ulonglong2* kr = (const ulonglong2*)(Ks + j*HEADC);
        ulonglong2 k0 = kr[0], k1 = kr[1], k2 = kr[2], k3 = kr[3];
        float e[2];
        #pragma unroll
        for (int u=0;u<2;u++){
            ull s = mul2(q2[u][0], k0.x);
            s = fma2r(q2[u][1], k0.y, s);
            s = fma2r(q2[u][2], k1.x, s);
            s = fma2r(q2[u][3], k1.y, s);
            s = fma2r(q2[u][4], k2.x, s);
            s = fma2r(q2[u][5], k2.y, s);
            s = fma2r(q2[u][6], k3.x, s);
            s = fma2r(q2[u][7], k3.y, s);
            float s0, s1; unpack2(s, s0, s1);
            e[u] = ex2_fast(s0 + s1);
            l[u] += e[u];
        }
        const ulonglong2* vr = (const ulonglong2*)(Vs + j*HEADC);
        ulonglong2 v0 = vr[0], v1 = vr[1], v2 = vr[2], v3 = vr[3];
        ull vv[8] = {v0.x,v0.y,v1.x,v1.y,v2.x,v2.y,v3.x,v3.y};
        #pragma unroll
        for (int u=0;u<2;u++){
            ull eb = pack1(e[u]);
            #pragma unroll
            for (int p=0;p<8;p++) a2[u][p] = fma2r(eb, vv[p], a2[u][p]);
        }
    }
    float* ap = g_za + ((size_t)n*256 + 128 + h*HEADC)*HWTOK;
    #pragma unroll
    for (int u=0;u<2;u++){
        int q = q0 + u*ATTN_ACT;
        float inv = 1.f / l[u];
        #pragma unroll
        for (int p=0;p<8;p++){
            float lo, hi; unpack2(a2[u][p], lo, hi);
            ap[(size_t)(2*p)*HWTOK + q]   = lo*inv;
            ap[(size_t)(2*p+1)*HWTOK + q] = hi*inv;
        }
    }
}

// ---------------- launch ----------------
extern "C" void kernel_launch(void* const* d_in, const int* in_sizes, int n_in,
                              void* d_out, int out_size)
{
    const float* x      = (const float*)d_in[0];
    const float* w_in   = (const float*)d_in[1];
    const float* b_in   = (const float*)d_in[2];
    const float* w_conv = (const float*)d_in[3];
    const float* b_conv = (const float*)d_in[4];
    const float* wq     = (const float*)d_in[5];
    const float* wk     = (const float*)d_in[6];
    const float* wv     = (const float*)d_in[7];
    const float* w_i    = (const float*)d_in[8];
    const float* b_i    = (const float*)d_in[9];
    // d_in[10], d_in[11]: w_f/b_f unused (first timestep: f*c0 == 0)
    const float* w_g    = (const float*)d_in[12];
    const float* b_g    = (const float*)d_in[13];
    const float* w_o    = (const float*)d_in[14];
    const float* b_o    = (const float*)d_in[15];
    const float* w_out  = (const float*)d_in[16];
    const float* b_out  = (const float*)d_in[17];
    float* out = (float*)d_out;

    cudaFuncSetAttribute(attn_kernel, cudaFuncAttributeMaxDynamicSharedMemorySize, ATTN_SMEM);

    repack_all<<<1280,256>>>(w_in, wq, wk, wv, w_i, w_g, w_o, w_out, w_conv);

    inproj_kernel<<<dim3(21,NIMG),256>>>(x, b_in);                   // -> g_xtp
    conv3x3_kernel<<<dim3(18,NIMG),288>>>(b_conv);                   // -> g_za[:, :128]
    qkv_kernel<<<dim3(21,NIMG,3),256>>>();                           // -> g_q/g_k/g_v
    attn_kernel<<<dim3(2, NIMG*NHEAD), ATTN_THREADS, ATTN_SMEM>>>(); // -> g_za[:,128:]
    gates_gemm_kernel<<<dim3(21,NIMG,3),256>>>();                    // -> g_pre
    lstm_act_kernel<<<(ACT_N4+255)/256,256>>>(b_i, b_g, b_o);        // -> g_h
    outproj_kernel<<<dim3(21,NIMG),256>>>(b_out, out);               // -> d_out
}

// round 13
// speedup vs baseline: 1.1522x; 1.0497x over previous
#include <cuda_runtime.h>
#include <stdint.h>
#include <math.h>

#define NIMG 8
#define HH 36
#define WW 36
#define HWTOK 1296
#define HP 38
#define RCH 128
#define NHEAD 8
#define HEADC 16
#define LOG2E 1.44269504088896340736f

typedef unsigned long long ull;

// ---------------- scratch (device globals; zero-init at load) ----------------
__device__ float g_xtp[(size_t)NIMG*RCH*HP*HP];     // padded tanh(in-proj); borders stay 0
__device__ float g_za [(size_t)NIMG*256*HWTOK];     // [z | a]
__device__ float g_q  [(size_t)NIMG*RCH*HWTOK];
__device__ float g_k  [(size_t)NIMG*RCH*HWTOK];
__device__ float g_v  [(size_t)NIMG*RCH*HWTOK];
__device__ float g_h  [(size_t)NIMG*RCH*HWTOK];
__device__ float g_pre[3][(size_t)NIMG*RCH*HWTOK];  // gate pre-activations i,g,o

// transposed weights ([in][out], coalesced for GEMM smem fills)
__device__ float g_wt_in [128*128];
__device__ float g_wt_q  [128*128];
__device__ float g_wt_k  [128*128];
__device__ float g_wt_v  [128*128];
__device__ float g_wt_out[128*128];
__device__ float g_wt_i  [256*128];
__device__ float g_wt_g  [256*128];
__device__ float g_wt_o  [256*128];
__device__ float g_wt_conv[1152*128];               // [(ci*9+tap)][o], ci<128 only

// ---------------- helpers ----------------
__device__ __forceinline__ float tanh_fast(float x){
    float r; asm("tanh.approx.f32 %0, %1;" : "=f"(r) : "f"(x)); return r;
}
__device__ __forceinline__ float sigmoid_fast(float x){
    return 0.5f * tanh_fast(0.5f * x) + 0.5f;
}
__device__ __forceinline__ float ex2_fast(float x){
    float r; asm("ex2.approx.f32 %0, %1;" : "=f"(r) : "f"(x)); return r;
}
__device__ __forceinline__ ull pack2(float a, float b){
    ull r; asm("mov.b64 %0, {%1,%2};" : "=l"(r) : "f"(a), "f"(b)); return r;
}
__device__ __forceinline__ ull pack1(float a){
    ull r; asm("mov.b64 %0, {%1,%1};" : "=l"(r) : "f"(a)); return r;
}
__device__ __forceinline__ void unpack2(ull v, float& a, float& b){
    asm("mov.b64 {%0,%1}, %2;" : "=f"(a), "=f"(b) : "l"(v));
}
__device__ __forceinline__ ull mul2(ull a, ull b){
    ull d; asm("mul.rn.f32x2 %0, %1, %2;" : "=l"(d) : "l"(a), "l"(b)); return d;
}
__device__ __forceinline__ ull add2(ull a, ull b){
    ull d; asm("add.rn.f32x2 %0, %1, %2;" : "=l"(d) : "l"(a), "l"(b)); return d;
}
__device__ __forceinline__ ull fma2r(ull a, ull b, ull c){
    ull d; asm("fma.rn.f32x2 %0, %1, %2, %3;" : "=l"(d) : "l"(a), "l"(b), "l"(c)); return d;
}
__device__ __forceinline__ void cpasync16(void* smem_dst, const void* gmem_src, bool pred){
    unsigned int dst = (unsigned int)__cvta_generic_to_shared(smem_dst);
    int sz = pred ? 16 : 0;
    asm volatile("cp.async.cg.shared.global [%0], [%1], 16, %2;"
                 :: "r"(dst), "l"(gmem_src), "r"(sz) : "memory");
}
__device__ __forceinline__ void cp_commit(){
    asm volatile("cp.async.commit_group;" ::: "memory");
}
__device__ __forceinline__ void cp_wait0(){
    asm volatile("cp.async.wait_group 0;" ::: "memory");
}
__device__ __forceinline__ void cp_wait1(){
    asm volatile("cp.async.wait_group 1;" ::: "memory");
}

// ---------------- weight repack ----------------
__global__ void repack_all(const float* __restrict__ w_in, const float* __restrict__ wq,
                           const float* __restrict__ wk,   const float* __restrict__ wv,
                           const float* __restrict__ w_i,  const float* __restrict__ w_g,
                           const float* __restrict__ w_o,  const float* __restrict__ w_out,
                           const float* __restrict__ w_conv)
{
    int idx = blockIdx.x*256 + threadIdx.x;
    if (idx < 5*16384) {
        int m = idx >> 14; int r = idx & 16383; int o = r >> 7; int i = r & 127;
        float v;
        if      (m==0) v = w_in[r];
        else if (m==1) v = wq[r];
        else if (m==2) v = wk[r];
        else if (m==3) v = wv[r];
        else           v = w_out[r];
        float* d = (m==0)?g_wt_in:(m==1)?g_wt_q:(m==2)?g_wt_k:(m==3)?g_wt_v:g_wt_out;
        d[i*128+o] = v;
    } else if (idx < 5*16384 + 3*32768) {
        int r = idx - 5*16384; int m = r >> 15; int rr = r & 32767;
        int o = rr >> 8; int i = rr & 255;    // src [128][256]
        float v = (m==0) ? w_i[rr] : (m==1) ? w_g[rr] : w_o[rr];
        float* d = (m==0)?g_wt_i:(m==1)?g_wt_g:g_wt_o;
        d[i*128+o] = v;
    } else if (idx < 5*16384 + 3*32768 + 147456) {
        int r = idx - (5*16384 + 3*32768);
        int o = r / 1152; int rem = r - o*1152;         // rem = ci*9+tap, ci<128
        g_wt_conv[rem*128 + o] = w_conv[(size_t)o*2304 + rem];
    }
}

// ---------------- async GEMM core: 64 tok x 128 out, 3-stage cp.async, 1 sync/step ----------------
template<int KSTEPS>
__device__ __forceinline__ void gemm_core(const float* __restrict__ xn,
                                          const float* __restrict__ wt,
                                          int t0, ull (&acc2)[4][4],
                                          float (*xs)[16][64], float (*ws)[16][128])
{
    const int tid = threadIdx.x;
    const int tt = tid & 15;
    const int og = tid >> 4;
    const int xi = tid >> 4;                 // x row (k-index within slice)
    const int xq = tid & 15;                 // token quad
    const bool xok = (t0 + xq*4) < HWTOK;
    const int wi = tid >> 5;                 // w row for first half
    const int wq = tid & 31;                 // w quad

    // prologue: stages 0 and 1
    for (int st=0; st<2; st++){
        int kc = st*16;
        cpasync16(&xs[st][xi][xq*4], xn + (size_t)(kc+xi)*HWTOK + t0 + xq*4, xok);
        cpasync16(&ws[st][wi][wq*4],   wt + (size_t)(kc+wi)*128   + wq*4, true);
        cpasync16(&ws[st][wi+8][wq*4], wt + (size_t)(kc+wi+8)*128 + wq*4, true);
        cp_commit();
    }

    for (int s=0; s<KSTEPS; s++){
        cp_wait1();
        __syncthreads();
        // Writing stage (s+2)%3 is safe: its previous content (stage s-1) was
        // consumed before this barrier by every thread.
        if (s+2 < KSTEPS){
            const int st = (s+2)%3, kc = (s+2)*16;
            cpasync16(&xs[st][xi][xq*4], xn + (size_t)(kc+xi)*HWTOK + t0 + xq*4, xok);
            cpasync16(&ws[st][wi][wq*4],   wt + (size_t)(kc+wi)*128   + wq*4, true);
            cpasync16(&ws[st][wi+8][wq*4], wt + (size_t)(kc+wi+8)*128 + wq*4, true);
        }
        cp_commit();
        const int b = s%3;
        #pragma unroll
        for (int i=0;i<16;i++){
            float4 xv = *(const float4*)&xs[b][i][tt*4];
            ull xb[4] = {pack1(xv.x), pack1(xv.y), pack1(xv.z), pack1(xv.w)};
            ulonglong2 w0 = *(const ulonglong2*)&ws[b][i][og*8];
            ulonglong2 w1 = *(const ulonglong2*)&ws[b][i][og*8+4];
            ull wp[4] = {w0.x, w0.y, w1.x, w1.y};
            #pragma unroll
            for (int p=0;p<4;p++)
                #pragma unroll
                for (int t=0;t<4;t++)
                    acc2[p][t] = fma2r(xb[t], wp[p], acc2[p][t]);
        }
        // no trailing sync: next iteration's top barrier provides the fence
    }
}

// ---------------- in-proj: x -> tanh -> padded g_xtp ----------------
__global__ __launch_bounds__(256) void inproj_kernel(const float* __restrict__ x,
                                                     const float* __restrict__ bias)
{
    __shared__ float xs[3][16][64];
    __shared__ float ws[3][16][128];
    const int n  = blockIdx.y;
    const int t0 = blockIdx.x * 64;
    const int tt = threadIdx.x & 15;
    const int og = threadIdx.x >> 4;
    ull acc2[4][4];
    #pragma unroll
    for (int p=0;p<4;p++) for (int t=0;t<4;t++) acc2[p][t] = 0ull;
    gemm_core<8>(x + (size_t)n*128*HWTOK, g_wt_in, t0, acc2, xs, ws);
    #pragma unroll
    for (int p=0;p<4;p++){
        int oc0 = og*8 + 2*p;
        float b0 = bias[oc0], b1 = bias[oc0+1];
        #pragma unroll
        for (int t=0;t<4;t++){
            int gt = t0 + tt*4 + t;
            if (gt >= HWTOK) continue;
            float v0, v1; unpack2(acc2[p][t], v0, v1);
            int y = gt/WW, xc = gt - y*WW;
            size_t base = (((size_t)n*RCH)*HP + (y+1))*HP + (xc+1);
            g_xtp[base + (size_t)oc0*HP*HP]     = tanh_fast(v0 + b0);
            g_xtp[base + (size_t)(oc0+1)*HP*HP] = tanh_fast(v1 + b1);
        }
    }
}

// ---------------- qkv: z selects matrix; raw store ----------------
__global__ __launch_bounds__(256) void qkv_kernel()
{
    __shared__ float xs[3][16][64];
    __shared__ float ws[3][16][128];
    const int n  = blockIdx.y;
    const int z  = blockIdx.z;
    const int t0 = blockIdx.x * 64;
    const int tt = threadIdx.x & 15;
    const int og = threadIdx.x >> 4;
    const float* wt = (z==0) ? g_wt_q : (z==1) ? g_wt_k : g_wt_v;
    float* dst      = (z==0) ? g_q    : (z==1) ? g_k    : g_v;
    ull acc2[4][4];
    #pragma unroll
    for (int p=0;p<4;p++) for (int t=0;t<4;t++) acc2[p][t] = 0ull;
    gemm_core<8>(g_za + (size_t)n*256*HWTOK, wt, t0, acc2, xs, ws);
    #pragma unroll
    for (int p=0;p<4;p++){
        int oc0 = og*8 + 2*p;
        #pragma unroll
        for (int t=0;t<4;t++){
            int gt = t0 + tt*4 + t;
            if (gt >= HWTOK) continue;
            float v0, v1; unpack2(acc2[p][t], v0, v1);
            dst[((size_t)n*RCH+oc0)*HWTOK+gt]   = v0;
            dst[((size_t)n*RCH+oc0+1)*HWTOK+gt] = v1;
        }
    }
}

// ---------------- gates GEMM: z in {i,g,o}; raw store to g_pre ----------------
__global__ __launch_bounds__(256) void gates_gemm_kernel()
{
    __shared__ float xs[3][16][64];
    __shared__ float ws[3][16][128];
    const int n  = blockIdx.y;
    const int z  = blockIdx.z;
    const int t0 = blockIdx.x * 64;
    const int tt = threadIdx.x & 15;
    const int og = threadIdx.x >> 4;
    const float* wt = (z==0) ? g_wt_i : (z==1) ? g_wt_g : g_wt_o;
    float* dst = g_pre[z];
    ull acc2[4][4];
    #pragma unroll
    for (int p=0;p<4;p++) for (int t=0;t<4;t++) acc2[p][t] = 0ull;
    gemm_core<16>(g_za + (size_t)n*256*HWTOK, wt, t0, acc2, xs, ws);
    #pragma unroll
    for (int p=0;p<4;p++){
        int oc0 = og*8 + 2*p;
        #pragma unroll
        for (int t=0;t<4;t++){
            int gt = t0 + tt*4 + t;
            if (gt >= HWTOK) continue;
            float v0, v1; unpack2(acc2[p][t], v0, v1);
            dst[((size_t)n*RCH+oc0)*HWTOK+gt]   = v0;
            dst[((size_t)n*RCH+oc0+1)*HWTOK+gt] = v1;
        }
    }
}

// ---------------- LSTM activation: h = sigm(o) * tanh(sigm(i)*tanh(g)) ----------------
#define ACT_N4 (NIMG*RCH*(HWTOK/4))
__global__ __launch_bounds__(256) void lstm_act_kernel(const float* __restrict__ bi,
                                                       const float* __restrict__ bg,
                                                       const float* __restrict__ bo)
{
    int i4 = blockIdx.x*256 + threadIdx.x;
    if (i4 >= ACT_N4) return;
    int oc = (i4 / (HWTOK/4)) & 127;
    float bbi = bi[oc], bbg = bg[oc], bbo = bo[oc];
    float4 pi = ((const float4*)g_pre[0])[i4];
    float4 pg = ((const float4*)g_pre[1])[i4];
    float4 po = ((const float4*)g_pre[2])[i4];
    float4 r;
    r.x = sigmoid_fast(po.x+bbo) * tanh_fast(sigmoid_fast(pi.x+bbi) * tanh_fast(pg.x+bbg));
    r.y = sigmoid_fast(po.y+bbo) * tanh_fast(sigmoid_fast(pi.y+bbi) * tanh_fast(pg.y+bbg));
    r.z = sigmoid_fast(po.z+bbo) * tanh_fast(sigmoid_fast(pi.z+bbi) * tanh_fast(pg.z+bbg));
    r.w = sigmoid_fast(po.w+bbo) * tanh_fast(sigmoid_fast(pi.w+bbi) * tanh_fast(pg.w+bbg));
    ((float4*)g_h)[i4] = r;
}

// ---------------- out-proj ----------------
__global__ __launch_bounds__(256) void outproj_kernel(const float* __restrict__ bias,
                                                      float* __restrict__ outx)
{
    __shared__ float xs[3][16][64];
    __shared__ float ws[3][16][128];
    const int n  = blockIdx.y;
    const int t0 = blockIdx.x * 64;
    const int tt = threadIdx.x & 15;
    const int og = threadIdx.x >> 4;
    ull acc2[4][4];
    #pragma unroll
    for (int p=0;p<4;p++) for (int t=0;t<4;t++) acc2[p][t] = 0ull;
    gemm_core<8>(g_h + (size_t)n*128*HWTOK, g_wt_out, t0, acc2, xs, ws);
    #pragma unroll
    for (int p=0;p<4;p++){
        int oc0 = og*8 + 2*p;
        float b0 = bias[oc0], b1 = bias[oc0+1];
        #pragma unroll
        for (int t=0;t<4;t++){
            int gt = t0 + tt*4 + t;
            if (gt >= HWTOK) continue;
            float v0, v1; unpack2(acc2[p][t], v0, v1);
            outx[((size_t)n*RCH+oc0)*HWTOK+gt]   = v0 + b0;
            outx[((size_t)n*RCH+oc0+1)*HWTOK+gt] = v1 + b1;
        }
    }
}

// ---------------- conv3x3: weights via cp.async, x via regs ----------------
__global__ void conv3x3_kernel(const float* __restrict__ bias)
{
    __shared__ float xs[2][8][4][40];
    __shared__ float ws[2][8][9][128];
    const int n  = blockIdx.y;
    const int y0 = blockIdx.x*2;
    const int tid = threadIdx.x;        // 288 threads
    const int tg = tid % 9;
    const int og = tid / 9;
    ull acc2[2][2][4];
    #pragma unroll
    for (int yr=0;yr<2;yr++) for (int p=0;p<2;p++) for (int t=0;t<4;t++) acc2[yr][p][t]=0ull;

    const float* xp = g_xtp + (size_t)n*RCH*HP*HP;
    float xr[5];

    // prologue: stage 0
    #pragma unroll
    for (int r=0;r<5;r++){
        int idx = tid + r*288;
        if (idx < 1216){
            int ci = idx/152, rem = idx - ci*152, dy = rem/38, cx = rem - dy*38;
            xs[0][ci][dy][cx] = xp[(size_t)ci*HP*HP + (y0+dy)*HP + cx];
        }
    }
    #pragma unroll
    for (int r=0;r<8;r++)
        cpasync16(&((float4*)ws[0])[tid + r*288], ((const float4*)g_wt_conv) + tid + r*288, true);
    cp_commit();
    cp_wait0();
    __syncthreads();

    for (int s=0; s<16; s++){
        const int b = s&1, nb = b^1;
        if (s<15){
            const int kc=(s+1)*8;
            #pragma unroll
            for (int r=0;r<5;r++){
                int idx = tid + r*288;
                if (idx < 1216){
                    int ci = idx/152, rem = idx - ci*152, dy = rem/38, cx = rem - dy*38;
                    xr[r] = xp[(size_t)(kc+ci)*HP*HP + (y0+dy)*HP + cx];
                }
            }
            #pragma unroll
            for (int r=0;r<8;r++)
                cpasync16(&((float4*)ws[nb])[tid + r*288],
                          ((const float4*)(g_wt_conv + kc*1152)) + tid + r*288, true);
            cp_commit();
        }
        #pragma unroll
        for (int i=0;i<8;i++){
            ull xb[4][6];
            #pragma unroll
            for (int dy=0; dy<4; dy++){
                float4 x4 = *(const float4*)&xs[b][i][dy][tg*4];
                float2 x2 = *(const float2*)&xs[b][i][dy][tg*4+4];
                xb[dy][0]=pack1(x4.x); xb[dy][1]=pack1(x4.y); xb[dy][2]=pack1(x4.z);
                xb[dy][3]=pack1(x4.w); xb[dy][4]=pack1(x2.x); xb[dy][5]=pack1(x2.y);
            }
            #pragma unroll
            for (int dy=0;dy<3;dy++)
                #pragma unroll
                for (int dx=0;dx<3;dx++){
                    ulonglong2 w2 = *(const ulonglong2*)&ws[b][i][dy*3+dx][og*4];
                    #pragma unroll
                    for (int yr=0;yr<2;yr++)
                        #pragma unroll
                        for (int t=0;t<4;t++){
                            acc2[yr][0][t] = fma2r(xb[dy+yr][t+dx], w2.x, acc2[yr][0][t]);
                            acc2[yr][1][t] = fma2r(xb[dy+yr][t+dx], w2.y, acc2[yr][1][t]);
                        }
                }
        }
        if (s<15){
            #pragma unroll
            for (int r=0;r<5;r++){
                int idx = tid + r*288;
                if (idx < 1216){
                    int ci = idx/152, rem = idx - ci*152, dy = rem/38, cx = rem - dy*38;
                    xs[nb][ci][dy][cx] = xr[r];
                }
            }
            cp_wait0();
        }
        __syncthreads();
    }

    #pragma unroll
    for (int yr=0;yr<2;yr++){
        int y = y0 + yr;
        #pragma unroll
        for (int p=0;p<2;p++){
            int oc0 = og*4 + 2*p;
            float b0 = bias[oc0], b1 = bias[oc0+1];
            #pragma unroll
            for (int t=0;t<4;t++){
                int xc = tg*4+t;
                float v0, v1; unpack2(acc2[yr][p][t], v0, v1);
                g_za[((size_t)n*256 + oc0)*HWTOK + y*WW + xc]   = v0 + b0;
                g_za[((size_t)n*256 + oc0+1)*HWTOK + y*WW + xc] = v1 + b1;
            }
        }
    }
}

// ---------------- attention: K,V smem-resident (stride-20 rows), 2 q/thread ----------------
#define ATTN_THREADS 352
#define ATTN_ACT 324
#define KSTR 20
#define ATTN_SMEM (2*HWTOK*KSTR*4)

__global__ void attn_kernel()
{
    extern __shared__ float sm[];
    float* Ks = sm;                       // [1296][20] (16 used, 20 stride: 80B rows, 16B-aligned)
    float* Vs = sm + HWTOK*KSTR;
    const int nh = blockIdx.y; const int n = nh >> 3; const int h = nh & 7;
    const int tid = threadIdx.x;
    const float* kp = g_k + ((size_t)n*RCH + h*HEADC)*HWTOK;
    const float* vp = g_v + ((size_t)n*RCH + h*HEADC)*HWTOK;
    #pragma unroll
    for (int c=0;c<HEADC;c++){
        for (int j=tid;j<HWTOK;j+=ATTN_THREADS){
            Ks[j*KSTR+c] = kp[(size_t)c*HWTOK+j];
            Vs[j*KSTR+c] = vp[(size_t)c*HWTOK+j];
        }
    }
    __syncthreads();
    if (tid >= ATTN_ACT) return;

    const int q0 = blockIdx.x*648 + tid;     // q0, q0+324
    const float* qp = g_q + ((size_t)n*RCH + h*HEADC)*HWTOK;
    ull q2[2][8], a2[2][8], l2 = 0ull;
    #pragma unroll
    for (int u=0;u<2;u++){
        int q = q0 + u*ATTN_ACT;
        #pragma unroll
        for (int p=0;p<8;p++){
            q2[u][p] = pack2(qp[(size_t)(2*p)*HWTOK+q]*LOG2E,
                             qp[(size_t)(2*p+1)*HWTOK+q]*LOG2E);
            a2[u][p] = 0ull;
        }
    }
    #pragma unroll 2
    for (int j=0;j<HWTOK;j++){
        const ulonglong2* kr = (const ulonglong2*)(Ks + j*KSTR);
        ulonglong2 k0 = kr[0], k1 = kr[1], k2 = kr[2], k3 = kr[3];
        float e[2];
        #pragma unroll
        for (int u=0;u<2;u++){
            ull s = mul2(q2[u][0], k0.x);
            s = fma2r(q2[u][1], k0.y, s);
            s = fma2r(q2[u][2], k1.x, s);
            s = fma2r(q2[u][3], k1.y, s);
            s = fma2r(q2[u][4], k2.x, s);
            s = fma2r(q2[u][5], k2.y, s);
            s = fma2r(q2[u][6], k3.x, s);
            s = fma2r(q2[u][7], k3.y, s);
            float s0, s1; unpack2(s, s0, s1);
            e[u] = ex2_fast(s0 + s1);
        }
        l2 = add2(l2, pack2(e[0], e[1]));
        const ulonglong2* vr = (const ulonglong2*)(Vs + j*KSTR);
        ulonglong2 v0 = vr[0], v1 = vr[1], v2 = vr[2], v3 = vr[3];
        ull vv[8] = {v0.x,v0.y,v1.x,v1.y,v2.x,v2.y,v3.x,v3.y};
        #pragma unroll
        for (int u=0;u<2;u++){
            ull eb = pack1(e[u]);
            #pragma unroll
            for (int p=0;p<8;p++) a2[u][p] = fma2r(eb, vv[p], a2[u][p]);
        }
    }
    float l0, l1; unpack2(l2, l0, l1);
    float* ap = g_za + ((size_t)n*256 + 128 + h*HEADC)*HWTOK;
    #pragma unroll
    for (int u=0;u<2;u++){
        int q = q0 + u*ATTN_ACT;
        float inv = 1.f / ((u==0) ? l0 : l1);
        #pragma unroll
        for (int p=0;p<8;p++){
            float lo, hi; unpack2(a2[u][p], lo, hi);
            ap[(size_t)(2*p)*HWTOK + q]   = lo*inv;
            ap[(size_t)(2*p+1)*HWTOK + q] = hi*inv;
        }
    }
}

// ---------------- launch ----------------
extern "C" void kernel_launch(void* const* d_in, const int* in_sizes, int n_in,
                              void* d_out, int out_size)
{
    const float* x      = (const float*)d_in[0];
    const float* w_in   = (const float*)d_in[1];
    const float* b_in   = (const float*)d_in[2];
    const float* w_conv = (const float*)d_in[3];
    const float* b_conv = (const float*)d_in[4];
    const float* wq     = (const float*)d_in[5];
    const float* wk     = (const float*)d_in[6];
    const float* wv     = (const float*)d_in[7];
    const float* w_i    = (const float*)d_in[8];
    const float* b_i    = (const float*)d_in[9];
    // d_in[10], d_in[11]: w_f/b_f unused (first timestep: f*c0 == 0)
    const float* w_g    = (const float*)d_in[12];
    const float* b_g    = (const float*)d_in[13];
    const float* w_o    = (const float*)d_in[14];
    const float* b_o    = (const float*)d_in[15];
    const float* w_out  = (const float*)d_in[16];
    const float* b_out  = (const float*)d_in[17];
    float* out = (float*)d_out;

    cudaFuncSetAttribute(attn_kernel, cudaFuncAttributeMaxDynamicSharedMemorySize, ATTN_SMEM);

    repack_all<<<1280,256>>>(w_in, wq, wk, wv, w_i, w_g, w_o, w_out, w_conv);

    inproj_kernel<<<dim3(21,NIMG),256>>>(x, b_in);                   // -> g_xtp
    conv3x3_kernel<<<dim3(18,NIMG),288>>>(b_conv);                   // -> g_za[:, :128]
    qkv_kernel<<<dim3(21,NIMG,3),256>>>();                           // -> g_q/g_k/g_v
    attn_kernel<<<dim3(2, NIMG*NHEAD), ATTN_THREADS, ATTN_SMEM>>>(); // -> g_za[:,128:]
    gates_gemm_kernel<<<dim3(21,NIMG,3),256>>>();                    // -> g_pre
    lstm_act_kernel<<<(ACT_N4+255)/256,256>>>(b_i, b_g, b_o);        // -> g_h
    outproj_kernel<<<dim3(21,NIMG),256>>>(b_out, out);               // -> d_out
}